// round 6
// baseline (speedup 1.0000x reference)
#include <cuda_runtime.h>
#include <math.h>
#include <stdint.h>

// Problem constants
#define BB    256
#define HH    6
#define NN    2048
#define MM    64
#define DIN   128
#define WFLAT 12288          // H*N
#define DCAT  12416
#define DOUT  384
#define Y_N   1152           // 3*DOUT
#define MEM_ELEMS 131072     // N*M per batch
#define OUT_MEM_TOTAL 33554432  // B*N*M

// GEMM config: K-tiles of 32 floats; 388 tiles total; uneven split over 12
#define SPLITK 12
#define BKT 32
#define BMT 64
#define BNT 64
#define ASTR 36              // A tile stride (32 + 4 pad) -> LDSM conflict-free
#define BSTR 72              // B tile stride (64 + 8 pad) -> frag LDS conflict-free

// Scratch (static device memory; no allocation)
__device__ float g_Ypart[SPLITK * (size_t)BB * Y_N];  // 14.2 MB
__device__ float g_Ks[BB * DOUT];
__device__ float g_Es[BB * DOUT];
__device__ float g_As[BB * DOUT];

__device__ __forceinline__ float f2tf(float f) {
    unsigned u;
    asm("cvt.rna.tf32.f32 %0, %1;" : "=r"(u) : "f"(f));
    return __uint_as_float(u);
}

__device__ __forceinline__ unsigned s2u(const void* p) {
    return (unsigned)__cvta_generic_to_shared(p);
}

#define MMA_TF32(c, a, b0, b1)                                                     \
    asm volatile(                                                                  \
        "mma.sync.aligned.m16n8k8.row.col.f32.tf32.tf32.f32 "                      \
        "{%0,%1,%2,%3},{%4,%5,%6,%7},{%8,%9},{%0,%1,%2,%3};"                       \
        : "+f"(c[0]), "+f"(c[1]), "+f"(c[2]), "+f"(c[3])                           \
        : "r"(a[0]), "r"(a[1]), "r"(a[2]), "r"(a[3]), "r"(b0), "r"(b1))

#define LDSM_X4(r, addr)                                                           \
    asm volatile("ldmatrix.sync.aligned.m8n8.x4.shared.b16 {%0,%1,%2,%3}, [%4];"   \
                 : "=r"(r[0]), "=r"(r[1]), "=r"(r[2]), "=r"(r[3]) : "r"(addr))

// ---------------------------------------------------------------------------
// K1: split-K tf32 GEMM  Y[256,1152] = x[256,12416] @ [Wk|We|Wa]
// grid (4, 18, 12), 128 threads. A frags via ldmatrix, BKT=32,
// register double-buffered fragments (one 29-cyc LDS stall per 16 MMAs hidden).
// ---------------------------------------------------------------------------
__global__ __launch_bounds__(128) void gemm_kernel(
    const float* __restrict__ xw, const float* __restrict__ xin,
    const float* __restrict__ Wk, const float* __restrict__ We,
    const float* __restrict__ Wa)
{
    __shared__ float As[2][BMT * ASTR];   // 64 x 32 (+pad)
    __shared__ float Bs[2][BKT * BSTR];   // 32 x 64 (+pad)

    const int tid = threadIdx.x;
    const int mt = blockIdx.x, nt = blockIdx.y, z = blockIdx.z;
    const int m0 = mt * BMT;
    const int mat = nt / 6;
    const int n0col = (nt % 6) * BNT;
    const float* __restrict__ Wp = (mat == 0) ? Wk : ((mat == 1) ? We : Wa);

    // Uneven split-K: first 4 z's get 33 tiles, rest 32 (total 388)
    const int baseT = z * 32 + min(z, 4);
    const int cnt   = 32 + (z < 4 ? 1 : 0);
    const int k0    = baseT * BKT;

    const int wid = tid >> 5, lane = tid & 31;
    const int g = lane >> 2, t = lane & 3;
    const int wm = (wid & 1) * 32, wn = (wid >> 1) * 32;

    // LDSM per-lane address component (floats)
    const int aRowOff = (lane & 15) * ASTR + (lane >> 4) * 4;
    const unsigned sAs0 = s2u(&As[0][0]);
    const unsigned sAs1 = s2u(&As[1][0]);

    // Global-load coordinates
    const int arow = tid >> 3;          // base row
    const int akf4 = (tid & 7) * 4;     // k offset in floats
    const int bkr  = tid >> 4;          // base k row
    const int bnf4 = (tid & 15) * 4;    // n offset

    float acc[2][4][4];
#pragma unroll
    for (int i = 0; i < 2; i++)
#pragma unroll
        for (int j = 0; j < 4; j++)
#pragma unroll
            for (int q = 0; q < 4; q++) acc[i][j][q] = 0.0f;

    float4 ar[4], br[4];

#define GLOAD(it)                                                                  \
    do {                                                                           \
        int kb = k0 + (it) * BKT;                                                  \
        _Pragma("unroll")                                                          \
        for (int i = 0; i < 4; i++) {                                              \
            int row = arow + i * 16;                                               \
            int kg = kb + akf4;                                                    \
            if (kg < WFLAT)                                                        \
                ar[i] = *(const float4*)(xw + (size_t)(m0 + row) * WFLAT + kg);    \
            else                                                                   \
                ar[i] = *(const float4*)(xin + (size_t)(m0 + row) * DIN +          \
                                         (kg - WFLAT));                            \
        }                                                                          \
        _Pragma("unroll")                                                          \
        for (int i = 0; i < 4; i++) {                                              \
            int kr = bkr + i * 8;                                                  \
            br[i] = *(const float4*)(Wp + (size_t)(kb + kr) * DOUT + n0col + bnf4);\
        }                                                                          \
    } while (0)

#define STS(bufb)                                                                  \
    do {                                                                           \
        _Pragma("unroll")                                                          \
        for (int i = 0; i < 4; i++) {                                              \
            float4 v;                                                              \
            v.x = f2tf(ar[i].x); v.y = f2tf(ar[i].y);                              \
            v.z = f2tf(ar[i].z); v.w = f2tf(ar[i].w);                              \
            *(float4*)&As[bufb][(arow + i * 16) * ASTR + akf4] = v;                \
        }                                                                          \
        _Pragma("unroll")                                                          \
        for (int i = 0; i < 4; i++) {                                              \
            float4 v;                                                              \
            v.x = f2tf(br[i].x); v.y = f2tf(br[i].y);                              \
            v.z = f2tf(br[i].z); v.w = f2tf(br[i].w);                              \
            *(float4*)&Bs[bufb][(bkr + i * 8) * BSTR + bnf4] = v;                  \
        }                                                                          \
    } while (0)

    // Double-buffered fragment registers
    unsigned afr[2][2][4];   // [pipe][mf][4]
    unsigned bfr[2][4][2];   // [pipe][nf][2]

#define LDFRAG(pb, sA, bfb, koOff)                                                 \
    do {                                                                           \
        _Pragma("unroll")                                                          \
        for (int mf = 0; mf < 2; mf++) {                                           \
            unsigned addr = (sA) + 4u * ((wm + mf * 16) * ASTR + aRowOff + (koOff));\
            LDSM_X4(afr[pb][mf], addr);                                            \
        }                                                                          \
        _Pragma("unroll")                                                          \
        for (int nf = 0; nf < 4; nf++) {                                           \
            int c0 = wn + nf * 8 + g;                                              \
            bfr[pb][nf][0] = __float_as_uint(Bs[bfb][((koOff) + t) * BSTR + c0]);  \
            bfr[pb][nf][1] = __float_as_uint(Bs[bfb][((koOff) + t + 4) * BSTR + c0]);\
        }                                                                          \
    } while (0)

    GLOAD(0);
    STS(0);
    __syncthreads();
    LDFRAG(0, sAs0, 0, 0);

    for (int it = 0; it < cnt; ++it) {
        const bool more = (it + 1 < cnt);
        if (more) GLOAD(it + 1);

        const int bf = it & 1;
        const unsigned sA = (bf == 0) ? sAs0 : sAs1;
#pragma unroll
        for (int ko4 = 0; ko4 < 4; ko4++) {
            const int pb = ko4 & 1;
            if (ko4 < 3) LDFRAG(pb ^ 1, sA, bf, (ko4 + 1) * 8);
#pragma unroll
            for (int mf = 0; mf < 2; mf++)
#pragma unroll
                for (int nf = 0; nf < 4; nf++)
                    MMA_TF32(acc[mf][nf], afr[pb][mf], bfr[pb][nf][0], bfr[pb][nf][1]);
        }

        if (more) {
            const int nb = (it + 1) & 1;
            // Safe: buffer nb was last read before the sync at end of it-1.
            STS(nb);
            __syncthreads();
            const unsigned sAn = (nb == 0) ? sAs0 : sAs1;
            LDFRAG(0, sAn, nb, 0);
        }
    }

    // Epilogue: write partial tile (deterministic, no atomics)
    float* yp = g_Ypart + (size_t)z * (BB * Y_N);
#pragma unroll
    for (int mf = 0; mf < 2; mf++) {
#pragma unroll
        for (int nf = 0; nf < 4; nf++) {
            int row = m0 + wm + mf * 16 + g;
            int col = nt * BNT + wn + nf * 8 + 2 * t;
            float2 v0 = make_float2(acc[mf][nf][0], acc[mf][nf][1]);
            float2 v1 = make_float2(acc[mf][nf][2], acc[mf][nf][3]);
            *(float2*)(yp + (size_t)row * Y_N + col) = v0;
            *(float2*)(yp + (size_t)(row + 8) * Y_N + col) = v1;
        }
    }
#undef GLOAD
#undef STS
#undef LDFRAG
}

// ---------------------------------------------------------------------------
// K1b: reduce split-K partials, add bias, apply sigmoid for e/a
// ---------------------------------------------------------------------------
__global__ void reduce_act_kernel(const float* __restrict__ bk,
                                  const float* __restrict__ be,
                                  const float* __restrict__ ba)
{
    int idx = blockIdx.x * blockDim.x + threadIdx.x;
    float s = 0.0f;
#pragma unroll
    for (int z = 0; z < SPLITK; z++)
        s += g_Ypart[(size_t)z * (BB * Y_N) + idx];
    int row = idx / Y_N;
    int col = idx - row * Y_N;
    int mat = col / DOUT;
    int c = col - mat * DOUT;
    if (mat == 0) {
        g_Ks[row * DOUT + c] = s + bk[c];
    } else if (mat == 1) {
        float v = s + be[c];
        g_Es[row * DOUT + c] = 1.0f / (1.0f + __expf(-v));
    } else {
        float v = s + ba[c];
        g_As[row * DOUT + c] = 1.0f / (1.0f + __expf(-v));
    }
}

// ---------------------------------------------------------------------------
// K2: per-batch fused addressing + softmax + update (unchanged from R4)
// grid 256, 256 threads (8 warps), ~110.7 KB smem -> 2 CTAs/SM, one wave.
// ---------------------------------------------------------------------------
#define SST 9
#define TSTRIDE 68
#define NWARP 8
#define ATTN_SMEM_FLOATS (NN * SST + NWARP * 16 * TSTRIDE + 3 * DOUT + HH * NWARP + 8)

__global__ __launch_bounds__(256, 2) void attn_update_kernel(
    const float* __restrict__ memory, float* __restrict__ out_mem,
    float* __restrict__ out_w)
{
    extern __shared__ float sm[];
    float* scores2 = sm;
    float* tile    = scores2 + NN * SST;
    float* kn      = tile + NWARP * 16 * TSTRIDE;
    float* esm     = kn + DOUT;
    float* asm_    = esm + DOUT;
    float* red     = asm_ + DOUT;
    float* redh    = red + HH * NWARP;

    const int b = blockIdx.x;
    const int tid = threadIdx.x, wid = tid >> 5, lane = tid & 31;
    const int g = lane >> 2, t = lane & 3;

    for (int i = tid; i < DOUT; i += 256) {
        esm[i]  = g_Es[b * DOUT + i];
        asm_[i] = g_As[b * DOUT + i];
    }
    if (wid < HH) {
        float k0 = g_Ks[b * DOUT + wid * 64 + 2 * lane];
        float k1 = g_Ks[b * DOUT + wid * 64 + 2 * lane + 1];
        float ss = k0 * k0 + k1 * k1;
#pragma unroll
        for (int o = 16; o > 0; o >>= 1) ss += __shfl_xor_sync(0xffffffffu, ss, o);
        float rn = rsqrtf(ss);
        kn[wid * 64 + 2 * lane]     = k0 * rn;
        kn[wid * 64 + 2 * lane + 1] = k1 * rn;
    }
    __syncthreads();

    const float* __restrict__ memb = memory + (size_t)b * MEM_ELEMS;

    {
        unsigned kb0[8], kb1[8];
#pragma unroll
        for (int c = 0; c < 8; c++) {
            float v0 = (g < HH) ? kn[g * 64 + c * 8 + t] : 0.0f;
            float v1 = (g < HH) ? kn[g * 64 + c * 8 + t + 4] : 0.0f;
            kb0[c] = __float_as_uint(v0);
            kb1[c] = __float_as_uint(v1);
        }

        float* tileF = tile + wid * 16 * TSTRIDE;
        float4* tf4 = (float4*)tileF;

        for (int j = 0; j < 16; j++) {
            const int n0 = wid * 16 + j * 128;
#pragma unroll
            for (int i = 0; i < 8; i++) {
                int idx = lane + i * 32;
                int row = idx >> 4, q = idx & 15;
                tf4[row * 17 + q] =
                    *(const float4*)(memb + (size_t)(n0 + row) * MM + q * 4);
            }
            __syncwarp();

            float acc[4] = {0.f, 0.f, 0.f, 0.f};
            float ss0 = 0.f, ss1 = 0.f;
#pragma unroll
            for (int c = 0; c < 8; c++) {
                float a0 = tileF[g * TSTRIDE + c * 8 + t];
                float a1 = tileF[(g + 8) * TSTRIDE + c * 8 + t];
                float a2 = tileF[g * TSTRIDE + c * 8 + t + 4];
                float a3 = tileF[(g + 8) * TSTRIDE + c * 8 + t + 4];
                ss0 += a0 * a0 + a2 * a2;
                ss1 += a1 * a1 + a3 * a3;
                unsigned af[4] = {__float_as_uint(a0), __float_as_uint(a1),
                                  __float_as_uint(a2), __float_as_uint(a3)};
                MMA_TF32(acc, af, kb0[c], kb1[c]);
            }
            ss0 += __shfl_xor_sync(0xffffffffu, ss0, 1);
            ss0 += __shfl_xor_sync(0xffffffffu, ss0, 2);
            ss1 += __shfl_xor_sync(0xffffffffu, ss1, 1);
            ss1 += __shfl_xor_sync(0xffffffffu, ss1, 2);
            float rn0 = rsqrtf(ss0), rn1 = rsqrtf(ss1);

            scores2[(n0 + g) * SST + 2 * t]         = acc[0] * rn0;
            scores2[(n0 + g) * SST + 2 * t + 1]     = acc[1] * rn0;
            scores2[(n0 + g + 8) * SST + 2 * t]     = acc[2] * rn1;
            scores2[(n0 + g + 8) * SST + 2 * t + 1] = acc[3] * rn1;
            __syncwarp();
        }
    }
    __syncthreads();

    {
        float mx[HH];
#pragma unroll
        for (int h = 0; h < HH; h++) mx[h] = -1e30f;
        for (int i = tid; i < NN; i += 256)
#pragma unroll
            for (int h = 0; h < HH; h++)
                mx[h] = fmaxf(mx[h], scores2[i * SST + h]);
#pragma unroll
        for (int h = 0; h < HH; h++) {
#pragma unroll
            for (int o = 16; o > 0; o >>= 1)
                mx[h] = fmaxf(mx[h], __shfl_xor_sync(0xffffffffu, mx[h], o));
        }
        if (lane == 0)
#pragma unroll
            for (int h = 0; h < HH; h++) red[h * NWARP + wid] = mx[h];
        __syncthreads();
        if (wid == 0) {
#pragma unroll
            for (int h = 0; h < HH; h++) {
                float v = (lane < NWARP) ? red[h * NWARP + lane] : -1e30f;
#pragma unroll
                for (int o = 4; o > 0; o >>= 1)
                    v = fmaxf(v, __shfl_xor_sync(0xffffffffu, v, o));
                if (lane == 0) redh[h] = v;
            }
        }
        __syncthreads();

        float bmx[HH], sum[HH];
#pragma unroll
        for (int h = 0; h < HH; h++) { bmx[h] = redh[h]; sum[h] = 0.0f; }
        for (int i = tid; i < NN; i += 256) {
#pragma unroll
            for (int h = 0; h < HH; h++) {
                float e = __expf(scores2[i * SST + h] - bmx[h]);
                scores2[i * SST + h] = e;
                sum[h] += e;
            }
        }
#pragma unroll
        for (int h = 0; h < HH; h++) {
#pragma unroll
            for (int o = 16; o > 0; o >>= 1)
                sum[h] += __shfl_xor_sync(0xffffffffu, sum[h], o);
        }
        if (lane == 0)
#pragma unroll
            for (int h = 0; h < HH; h++) red[h * NWARP + wid] = sum[h];
        __syncthreads();
        if (wid == 0) {
#pragma unroll
            for (int h = 0; h < HH; h++) {
                float v = (lane < NWARP) ? red[h * NWARP + lane] : 0.0f;
#pragma unroll
                for (int o = 4; o > 0; o >>= 1)
                    v += __shfl_xor_sync(0xffffffffu, v, o);
                if (lane == 0) redh[h] = v;
            }
        }
        __syncthreads();

        float inv[HH];
#pragma unroll
        for (int h = 0; h < HH; h++) inv[h] = 1.0f / redh[h];
        for (int i = tid; i < NN; i += 256) {
#pragma unroll
            for (int h = 0; h < HH; h++) {
                float wv = scores2[i * SST + h] * inv[h];
                scores2[i * SST + h] = wv;
                out_w[(size_t)b * (HH * NN) + h * NN + i] = wv;
            }
        }
    }
    __syncthreads();

    {
        unsigned eb0[8], eb1[8], ab0[8], ab1[8];
#pragma unroll
        for (int mb2 = 0; mb2 < 8; mb2++) {
            eb0[mb2] = __float_as_uint(esm[t * 64 + mb2 * 8 + g]);
            ab0[mb2] = __float_as_uint(asm_[t * 64 + mb2 * 8 + g]);
            eb1[mb2] = __float_as_uint((t < 2) ? esm[(t + 4) * 64 + mb2 * 8 + g] : 0.0f);
            ab1[mb2] = __float_as_uint((t < 2) ? asm_[(t + 4) * 64 + mb2 * 8 + g] : 0.0f);
        }

        float* outm = out_mem + (size_t)b * MEM_ELEMS;

        for (int j = 0; j < 16; j++) {
            const int n0 = wid * 16 + j * 128;
            unsigned af[4];
            af[0] = __float_as_uint(scores2[(n0 + g) * SST + t]);
            af[1] = __float_as_uint(scores2[(n0 + g + 8) * SST + t]);
            af[2] = __float_as_uint(scores2[(n0 + g) * SST + t + 4]);
            af[3] = __float_as_uint(scores2[(n0 + g + 8) * SST + t + 4]);

            float er[8][4], ad[8][4];
#pragma unroll
            for (int mb2 = 0; mb2 < 8; mb2++) {
#pragma unroll
                for (int q = 0; q < 4; q++) { er[mb2][q] = 0.f; ad[mb2][q] = 0.f; }
                MMA_TF32(er[mb2], af, eb0[mb2], eb1[mb2]);
                MMA_TF32(ad[mb2], af, ab0[mb2], ab1[mb2]);
            }

            const float* mrow0 = memb + (size_t)(n0 + g) * MM;
            const float* mrow1 = memb + (size_t)(n0 + g + 8) * MM;
            float* orow0 = outm + (size_t)(n0 + g) * MM;
            float* orow1 = outm + (size_t)(n0 + g + 8) * MM;
#pragma unroll
            for (int mb2 = 0; mb2 < 8; mb2++) {
                float2 m0v = *(const float2*)(mrow0 + mb2 * 8 + 2 * t);
                float2 m1v = *(const float2*)(mrow1 + mb2 * 8 + 2 * t);
                float2 o0, o1;
                o0.x = m0v.x + (ad[mb2][0] - m0v.x * m0v.x * er[mb2][0]);
                o0.y = m0v.y + (ad[mb2][1] - m0v.y * m0v.y * er[mb2][1]);
                o1.x = m1v.x + (ad[mb2][2] - m1v.x * m1v.x * er[mb2][2]);
                o1.y = m1v.y + (ad[mb2][3] - m1v.y * m1v.y * er[mb2][3]);
                *(float2*)(orow0 + mb2 * 8 + 2 * t) = o0;
                *(float2*)(orow1 + mb2 * 8 + 2 * t) = o1;
            }
        }
    }
}

// ---------------------------------------------------------------------------
extern "C" void kernel_launch(void* const* d_in, const int* in_sizes, int n_in,
                              void* d_out, int out_size)
{
    const float* inputs = (const float*)d_in[0];
    const float* memory = (const float*)d_in[1];
    const float* w      = (const float*)d_in[2];
    const float* Wk     = (const float*)d_in[3];
    const float* bk     = (const float*)d_in[4];
    const float* We     = (const float*)d_in[5];
    const float* be     = (const float*)d_in[6];
    const float* Wa     = (const float*)d_in[7];
    const float* ba     = (const float*)d_in[8];

    float* out     = (float*)d_out;
    float* out_mem = out;                       // new_memory [B,N,M]
    float* out_w   = out + OUT_MEM_TOTAL;       // w_new      [B,H,N]

    dim3 g1(4, 18, SPLITK);
    gemm_kernel<<<g1, 128>>>(w, inputs, Wk, We, Wa);

    reduce_act_kernel<<<(BB * Y_N) / 256, 256>>>(bk, be, ba);

    const int smem_bytes = ATTN_SMEM_FLOATS * (int)sizeof(float);
    cudaFuncSetAttribute(attn_update_kernel,
                         cudaFuncAttributeMaxDynamicSharedMemorySize, smem_bytes);
    attn_update_kernel<<<BB, 256, smem_bytes>>>(memory, out_mem, out_w);
}

// round 7
// speedup vs baseline: 1.1965x; 1.1965x over previous
#include <cuda_runtime.h>
#include <math.h>
#include <stdint.h>

// Problem constants
#define BB    256
#define HH    6
#define NN    2048
#define MM    64
#define DIN   128
#define WFLAT 12288          // H*N
#define DCAT  12416
#define DOUT  384
#define Y_N   1152           // 3*DOUT
#define MEM_ELEMS 131072     // N*M per batch
#define OUT_MEM_TOTAL 33554432  // B*N*M

// GEMM config: CTA tile 128x64, warp tile 64x32, BKT=32, cp.async pipeline
#define SPLITK 16
#define BKT 32
#define BMT 128
#define BNT 64
#define ASTR 36              // A tile row stride (floats): LDSM conflict-free
#define BSTR 72              // B tile row stride (floats): LDS conflict-free
#define A_TILE_F (BMT * ASTR)   // 4608 floats
#define B_TILE_F (BKT * BSTR)   // 2304 floats
#define GEMM_SMEM_BYTES ((2 * (A_TILE_F + B_TILE_F)) * 4)   // 55296

// Scratch (static device memory; no allocation)
__device__ float g_Ypart[SPLITK * (size_t)BB * Y_N];  // 18.9 MB
__device__ float g_Ks[BB * DOUT];
__device__ float g_Es[BB * DOUT];
__device__ float g_As[BB * DOUT];

__device__ __forceinline__ unsigned s2u(const void* p) {
    return (unsigned)__cvta_generic_to_shared(p);
}

__device__ __forceinline__ void cpa16(uint32_t dst, const void* src) {
    asm volatile("cp.async.cg.shared.global [%0], [%1], 16;" :: "r"(dst), "l"(src));
}
#define CP_COMMIT() asm volatile("cp.async.commit_group;" ::: "memory")
#define CP_WAIT1()  asm volatile("cp.async.wait_group 1;" ::: "memory")

#define MMA_TF32(c, a, b0, b1)                                                     \
    asm volatile(                                                                  \
        "mma.sync.aligned.m16n8k8.row.col.f32.tf32.tf32.f32 "                      \
        "{%0,%1,%2,%3},{%4,%5,%6,%7},{%8,%9},{%0,%1,%2,%3};"                       \
        : "+f"(c[0]), "+f"(c[1]), "+f"(c[2]), "+f"(c[3])                           \
        : "r"(a[0]), "r"(a[1]), "r"(a[2]), "r"(a[3]), "r"(b0), "r"(b1))

#define LDSM_X4(r, addr)                                                           \
    asm volatile("ldmatrix.sync.aligned.m8n8.x4.shared.b16 {%0,%1,%2,%3}, [%4];"   \
                 : "=r"(r[0]), "=r"(r[1]), "=r"(r[2]), "=r"(r[3]) : "r"(addr))

// ---------------------------------------------------------------------------
// K1: split-K tf32 GEMM  Y[256,1152] = x[256,12416] @ [Wk|We|Wa]
// grid (2, 18, 16), 128 threads. cp.async double-buffered, raw fp32->tf32
// (no cvt), warp tile 64x32.
// ---------------------------------------------------------------------------
__global__ __launch_bounds__(128) void gemm_kernel(
    const float* __restrict__ xw, const float* __restrict__ xin,
    const float* __restrict__ Wk, const float* __restrict__ We,
    const float* __restrict__ Wa)
{
    extern __shared__ float smf[];
    float* As[2] = {smf, smf + A_TILE_F};
    float* Bs[2] = {smf + 2 * A_TILE_F, smf + 2 * A_TILE_F + B_TILE_F};
    const uint32_t sA32[2] = {s2u(As[0]), s2u(As[1])};
    const uint32_t sB32[2] = {s2u(Bs[0]), s2u(Bs[1])};

    const int tid = threadIdx.x;
    const int mt = blockIdx.x, nt = blockIdx.y, z = blockIdx.z;
    const int m0 = mt * BMT;
    const int mat = nt / 6;
    const int n0col = (nt % 6) * BNT;
    const float* __restrict__ Wp = (mat == 0) ? Wk : ((mat == 1) ? We : Wa);

    // Uneven split-K over 388 32-float K-tiles: z<4 -> 25, else 24
    const int baseT = z * 24 + min(z, 4);
    const int cnt   = 24 + (z < 4 ? 1 : 0);
    const int k0    = baseT * BKT;

    const int wid = tid >> 5, lane = tid & 31;
    const int g = lane >> 2, t = lane & 3;
    const int wm = (wid & 1) * 64, wn = (wid >> 1) * 32;

    // LDSM per-lane address component (floats)
    const int aRowOff = (lane & 15) * ASTR + (lane >> 4) * 4;

    // Async-copy coordinates
    const int arow = tid >> 3;          // A: 8 chunks/thread, rows tid>>3 + i*16
    const int ac4  = (tid & 7) * 4;     // A: k offset (floats)
    const int brow = tid >> 4;          // B: 4 chunks/thread, rows tid>>4 + i*8
    const int bc4  = (tid & 15) * 4;    // B: n offset (floats)

    float acc[4][4][4];
#pragma unroll
    for (int i = 0; i < 4; i++)
#pragma unroll
        for (int j = 0; j < 4; j++)
#pragma unroll
            for (int q = 0; q < 4; q++) acc[i][j][q] = 0.0f;

#define LOADT(it)                                                                  \
    do {                                                                           \
        const int buf = (it) & 1;                                                  \
        int kb = k0 + (it) * BKT;                                                  \
        int kg = kb + ac4;                                                         \
        _Pragma("unroll")                                                          \
        for (int i = 0; i < 8; i++) {                                              \
            int row = arow + i * 16;                                               \
            uint32_t dst = sA32[buf] + 4u * (row * ASTR + ac4);                    \
            const float* src = (kg < WFLAT)                                        \
                ? (xw + (size_t)(m0 + row) * WFLAT + kg)                           \
                : (xin + (size_t)(m0 + row) * DIN + (kg - WFLAT));                 \
            cpa16(dst, src);                                                       \
        }                                                                          \
        _Pragma("unroll")                                                          \
        for (int i = 0; i < 4; i++) {                                              \
            int kr = brow + i * 8;                                                 \
            uint32_t dst = sB32[buf] + 4u * (kr * BSTR + bc4);                     \
            cpa16(dst, Wp + (size_t)(kb + kr) * DOUT + n0col + bc4);               \
        }                                                                          \
    } while (0)

    LOADT(0);
    CP_COMMIT();
    if (cnt > 1) LOADT(1);
    CP_COMMIT();

    for (int it = 0; it < cnt; ++it) {
        CP_WAIT1();
        __syncthreads();

        const int bf = it & 1;
        const uint32_t sA = sA32[bf];
        const float* __restrict__ Bsf = Bs[bf];
#pragma unroll
        for (int ko = 0; ko < BKT; ko += 8) {
            unsigned af[4][4];
#pragma unroll
            for (int mf = 0; mf < 4; mf++) {
                unsigned addr = sA + 4u * ((wm + mf * 16) * ASTR + aRowOff + ko);
                LDSM_X4(af[mf], addr);
            }
            unsigned bfr[4][2];
#pragma unroll
            for (int nf = 0; nf < 4; nf++) {
                int c0 = wn + nf * 8 + g;
                bfr[nf][0] = __float_as_uint(Bsf[(ko + t) * BSTR + c0]);
                bfr[nf][1] = __float_as_uint(Bsf[(ko + t + 4) * BSTR + c0]);
            }
#pragma unroll
            for (int mf = 0; mf < 4; mf++)
#pragma unroll
                for (int nf = 0; nf < 4; nf++)
                    MMA_TF32(acc[mf][nf], af[mf], bfr[nf][0], bfr[nf][1]);
        }

        __syncthreads();
        if (it + 2 < cnt) LOADT(it + 2);
        CP_COMMIT();
    }

    // Epilogue: write partial tile (deterministic, no atomics)
    float* yp = g_Ypart + (size_t)z * (BB * Y_N);
#pragma unroll
    for (int mf = 0; mf < 4; mf++) {
#pragma unroll
        for (int nf = 0; nf < 4; nf++) {
            int row = m0 + wm + mf * 16 + g;
            int col = nt * BNT + wn + nf * 8 + 2 * t;
            float2 v0 = make_float2(acc[mf][nf][0], acc[mf][nf][1]);
            float2 v1 = make_float2(acc[mf][nf][2], acc[mf][nf][3]);
            *(float2*)(yp + (size_t)row * Y_N + col) = v0;
            *(float2*)(yp + (size_t)(row + 8) * Y_N + col) = v1;
        }
    }
#undef LOADT
}

// ---------------------------------------------------------------------------
// K1b: reduce split-K partials, add bias, apply sigmoid for e/a
// ---------------------------------------------------------------------------
__global__ void reduce_act_kernel(const float* __restrict__ bk,
                                  const float* __restrict__ be,
                                  const float* __restrict__ ba)
{
    int idx = blockIdx.x * blockDim.x + threadIdx.x;
    float s = 0.0f;
#pragma unroll
    for (int z = 0; z < SPLITK; z++)
        s += g_Ypart[(size_t)z * (BB * Y_N) + idx];
    int row = idx / Y_N;
    int col = idx - row * Y_N;
    int mat = col / DOUT;
    int c = col - mat * DOUT;
    if (mat == 0) {
        g_Ks[row * DOUT + c] = s + bk[c];
    } else if (mat == 1) {
        float v = s + be[c];
        g_Es[row * DOUT + c] = 1.0f / (1.0f + __expf(-v));
    } else {
        float v = s + ba[c];
        g_As[row * DOUT + c] = 1.0f / (1.0f + __expf(-v));
    }
}

// ---------------------------------------------------------------------------
// K2: per-batch fused addressing + softmax + update (unchanged; passing)
// grid 256, 256 threads (8 warps), ~110.7 KB smem -> 2 CTAs/SM, one wave.
// ---------------------------------------------------------------------------
#define SST 9
#define TSTRIDE 68
#define NWARP 8
#define ATTN_SMEM_FLOATS (NN * SST + NWARP * 16 * TSTRIDE + 3 * DOUT + HH * NWARP + 8)

__global__ __launch_bounds__(256, 2) void attn_update_kernel(
    const float* __restrict__ memory, float* __restrict__ out_mem,
    float* __restrict__ out_w)
{
    extern __shared__ float sm[];
    float* scores2 = sm;
    float* tile    = scores2 + NN * SST;
    float* kn      = tile + NWARP * 16 * TSTRIDE;
    float* esm     = kn + DOUT;
    float* asm_    = esm + DOUT;
    float* red     = asm_ + DOUT;
    float* redh    = red + HH * NWARP;

    const int b = blockIdx.x;
    const int tid = threadIdx.x, wid = tid >> 5, lane = tid & 31;
    const int g = lane >> 2, t = lane & 3;

    for (int i = tid; i < DOUT; i += 256) {
        esm[i]  = g_Es[b * DOUT + i];
        asm_[i] = g_As[b * DOUT + i];
    }
    if (wid < HH) {
        float k0 = g_Ks[b * DOUT + wid * 64 + 2 * lane];
        float k1 = g_Ks[b * DOUT + wid * 64 + 2 * lane + 1];
        float ss = k0 * k0 + k1 * k1;
#pragma unroll
        for (int o = 16; o > 0; o >>= 1) ss += __shfl_xor_sync(0xffffffffu, ss, o);
        float rn = rsqrtf(ss);
        kn[wid * 64 + 2 * lane]     = k0 * rn;
        kn[wid * 64 + 2 * lane + 1] = k1 * rn;
    }
    __syncthreads();

    const float* __restrict__ memb = memory + (size_t)b * MEM_ELEMS;

    {
        unsigned kb0[8], kb1[8];
#pragma unroll
        for (int c = 0; c < 8; c++) {
            float v0 = (g < HH) ? kn[g * 64 + c * 8 + t] : 0.0f;
            float v1 = (g < HH) ? kn[g * 64 + c * 8 + t + 4] : 0.0f;
            kb0[c] = __float_as_uint(v0);
            kb1[c] = __float_as_uint(v1);
        }

        float* tileF = tile + wid * 16 * TSTRIDE;
        float4* tf4 = (float4*)tileF;

        for (int j = 0; j < 16; j++) {
            const int n0 = wid * 16 + j * 128;
#pragma unroll
            for (int i = 0; i < 8; i++) {
                int idx = lane + i * 32;
                int row = idx >> 4, q = idx & 15;
                tf4[row * 17 + q] =
                    *(const float4*)(memb + (size_t)(n0 + row) * MM + q * 4);
            }
            __syncwarp();

            float acc[4] = {0.f, 0.f, 0.f, 0.f};
            float ss0 = 0.f, ss1 = 0.f;
#pragma unroll
            for (int c = 0; c < 8; c++) {
                float a0 = tileF[g * TSTRIDE + c * 8 + t];
                float a1 = tileF[(g + 8) * TSTRIDE + c * 8 + t];
                float a2 = tileF[g * TSTRIDE + c * 8 + t + 4];
                float a3 = tileF[(g + 8) * TSTRIDE + c * 8 + t + 4];
                ss0 += a0 * a0 + a2 * a2;
                ss1 += a1 * a1 + a3 * a3;
                unsigned af[4] = {__float_as_uint(a0), __float_as_uint(a1),
                                  __float_as_uint(a2), __float_as_uint(a3)};
                MMA_TF32(acc, af, kb0[c], kb1[c]);
            }
            ss0 += __shfl_xor_sync(0xffffffffu, ss0, 1);
            ss0 += __shfl_xor_sync(0xffffffffu, ss0, 2);
            ss1 += __shfl_xor_sync(0xffffffffu, ss1, 1);
            ss1 += __shfl_xor_sync(0xffffffffu, ss1, 2);
            float rn0 = rsqrtf(ss0), rn1 = rsqrtf(ss1);

            scores2[(n0 + g) * SST + 2 * t]         = acc[0] * rn0;
            scores2[(n0 + g) * SST + 2 * t + 1]     = acc[1] * rn0;
            scores2[(n0 + g + 8) * SST + 2 * t]     = acc[2] * rn1;
            scores2[(n0 + g + 8) * SST + 2 * t + 1] = acc[3] * rn1;
            __syncwarp();
        }
    }
    __syncthreads();

    {
        float mx[HH];
#pragma unroll
        for (int h = 0; h < HH; h++) mx[h] = -1e30f;
        for (int i = tid; i < NN; i += 256)
#pragma unroll
            for (int h = 0; h < HH; h++)
                mx[h] = fmaxf(mx[h], scores2[i * SST + h]);
#pragma unroll
        for (int h = 0; h < HH; h++) {
#pragma unroll
            for (int o = 16; o > 0; o >>= 1)
                mx[h] = fmaxf(mx[h], __shfl_xor_sync(0xffffffffu, mx[h], o));
        }
        if (lane == 0)
#pragma unroll
            for (int h = 0; h < HH; h++) red[h * NWARP + wid] = mx[h];
        __syncthreads();
        if (wid == 0) {
#pragma unroll
            for (int h = 0; h < HH; h++) {
                float v = (lane < NWARP) ? red[h * NWARP + lane] : -1e30f;
#pragma unroll
                for (int o = 4; o > 0; o >>= 1)
                    v = fmaxf(v, __shfl_xor_sync(0xffffffffu, v, o));
                if (lane == 0) redh[h] = v;
            }
        }
        __syncthreads();

        float bmx[HH], sum[HH];
#pragma unroll
        for (int h = 0; h < HH; h++) { bmx[h] = redh[h]; sum[h] = 0.0f; }
        for (int i = tid; i < NN; i += 256) {
#pragma unroll
            for (int h = 0; h < HH; h++) {
                float e = __expf(scores2[i * SST + h] - bmx[h]);
                scores2[i * SST + h] = e;
                sum[h] += e;
            }
        }
#pragma unroll
        for (int h = 0; h < HH; h++) {
#pragma unroll
            for (int o = 16; o > 0; o >>= 1)
                sum[h] += __shfl_xor_sync(0xffffffffu, sum[h], o);
        }
        if (lane == 0)
#pragma unroll
            for (int h = 0; h < HH; h++) red[h * NWARP + wid] = sum[h];
        __syncthreads();
        if (wid == 0) {
#pragma unroll
            for (int h = 0; h < HH; h++) {
                float v = (lane < NWARP) ? red[h * NWARP + lane] : 0.0f;
#pragma unroll
                for (int o = 4; o > 0; o >>= 1)
                    v += __shfl_xor_sync(0xffffffffu, v, o);
                if (lane == 0) redh[h] = v;
            }
        }
        __syncthreads();

        float inv[HH];
#pragma unroll
        for (int h = 0; h < HH; h++) inv[h] = 1.0f / redh[h];
        for (int i = tid; i < NN; i += 256) {
#pragma unroll
            for (int h = 0; h < HH; h++) {
                float wv = scores2[i * SST + h] * inv[h];
                scores2[i * SST + h] = wv;
                out_w[(size_t)b * (HH * NN) + h * NN + i] = wv;
            }
        }
    }
    __syncthreads();

    {
        unsigned eb0[8], eb1[8], ab0[8], ab1[8];
#pragma unroll
        for (int mb2 = 0; mb2 < 8; mb2++) {
            eb0[mb2] = __float_as_uint(esm[t * 64 + mb2 * 8 + g]);
            ab0[mb2] = __float_as_uint(asm_[t * 64 + mb2 * 8 + g]);
            eb1[mb2] = __float_as_uint((t < 2) ? esm[(t + 4) * 64 + mb2 * 8 + g] : 0.0f);
            ab1[mb2] = __float_as_uint((t < 2) ? asm_[(t + 4) * 64 + mb2 * 8 + g] : 0.0f);
        }

        float* outm = out_mem + (size_t)b * MEM_ELEMS;

        for (int j = 0; j < 16; j++) {
            const int n0 = wid * 16 + j * 128;
            unsigned af[4];
            af[0] = __float_as_uint(scores2[(n0 + g) * SST + t]);
            af[1] = __float_as_uint(scores2[(n0 + g + 8) * SST + t]);
            af[2] = __float_as_uint(scores2[(n0 + g) * SST + t + 4]);
            af[3] = __float_as_uint(scores2[(n0 + g + 8) * SST + t + 4]);

            float er[8][4], ad[8][4];
#pragma unroll
            for (int mb2 = 0; mb2 < 8; mb2++) {
#pragma unroll
                for (int q = 0; q < 4; q++) { er[mb2][q] = 0.f; ad[mb2][q] = 0.f; }
                MMA_TF32(er[mb2], af, eb0[mb2], eb1[mb2]);
                MMA_TF32(ad[mb2], af, ab0[mb2], ab1[mb2]);
            }

            const float* mrow0 = memb + (size_t)(n0 + g) * MM;
            const float* mrow1 = memb + (size_t)(n0 + g + 8) * MM;
            float* orow0 = outm + (size_t)(n0 + g) * MM;
            float* orow1 = outm + (size_t)(n0 + g + 8) * MM;
#pragma unroll
            for (int mb2 = 0; mb2 < 8; mb2++) {
                float2 m0v = *(const float2*)(mrow0 + mb2 * 8 + 2 * t);
                float2 m1v = *(const float2*)(mrow1 + mb2 * 8 + 2 * t);
                float2 o0, o1;
                o0.x = m0v.x + (ad[mb2][0] - m0v.x * m0v.x * er[mb2][0]);
                o0.y = m0v.y + (ad[mb2][1] - m0v.y * m0v.y * er[mb2][1]);
                o1.x = m1v.x + (ad[mb2][2] - m1v.x * m1v.x * er[mb2][2]);
                o1.y = m1v.y + (ad[mb2][3] - m1v.y * m1v.y * er[mb2][3]);
                *(float2*)(orow0 + mb2 * 8 + 2 * t) = o0;
                *(float2*)(orow1 + mb2 * 8 + 2 * t) = o1;
            }
        }
    }
}

// ---------------------------------------------------------------------------
extern "C" void kernel_launch(void* const* d_in, const int* in_sizes, int n_in,
                              void* d_out, int out_size)
{
    const float* inputs = (const float*)d_in[0];
    const float* memory = (const float*)d_in[1];
    const float* w      = (const float*)d_in[2];
    const float* Wk     = (const float*)d_in[3];
    const float* bk     = (const float*)d_in[4];
    const float* We     = (const float*)d_in[5];
    const float* be     = (const float*)d_in[6];
    const float* Wa     = (const float*)d_in[7];
    const float* ba     = (const float*)d_in[8];

    float* out     = (float*)d_out;
    float* out_mem = out;                       // new_memory [B,N,M]
    float* out_w   = out + OUT_MEM_TOTAL;       // w_new      [B,H,N]

    cudaFuncSetAttribute(gemm_kernel,
                         cudaFuncAttributeMaxDynamicSharedMemorySize,
                         GEMM_SMEM_BYTES);
    dim3 g1(2, 18, SPLITK);
    gemm_kernel<<<g1, 128, GEMM_SMEM_BYTES>>>(w, inputs, Wk, We, Wa);

    reduce_act_kernel<<<(BB * Y_N) / 256, 256>>>(bk, be, ba);

    const int smem_bytes = ATTN_SMEM_FLOATS * (int)sizeof(float);
    cudaFuncSetAttribute(attn_update_kernel,
                         cudaFuncAttributeMaxDynamicSharedMemorySize, smem_bytes);
    attn_update_kernel<<<BB, 256, smem_bytes>>>(memory, out_mem, out_w);
}